// round 14
// baseline (speedup 1.0000x reference)
#include <cuda_runtime.h>
#include <cuda_fp16.h>
#include <cuda_fp8.h>
#include <math.h>

// Problem constants (match reference)
#define NN 50000
#define EG 800000
#define EE (EG + NN)   // edges + self loops = 850000
#define FD 128
#define PP 200000
#define ALPHA 0.1f

// ---------------------------------------------------------------------------
// Device scratch (no cudaMalloc allowed)
// ---------------------------------------------------------------------------
__device__ int   g_cnt[NN];
__device__ int   g_rowptr[NN + 1];
__device__ int   g_cursor[NN];
__device__ float g_dinv[NN];
__device__ uint2 g_meta[EE];                    // (col, half2(0.9*w, 0.9*w))
__device__ uint2 g_x0h[(size_t)NN * 32];        // fp16 teleport anchor (4 half/uint2 lane chunk)
__device__ float g_Hg[(size_t)NN * FD];         // fp32 final-prop output
__device__ unsigned g_f1[(size_t)NN * 32];      // fp8 ping (4 e4m3 / uint, 128B row)
__device__ unsigned g_f2[(size_t)NN * 32];      // fp8 pong

// ---------------------------------------------------------------------------
// CSR build
// ---------------------------------------------------------------------------
__global__ void k_init() {
    int v = blockIdx.x * blockDim.x + threadIdx.x;
    if (v < NN) g_cnt[v] = 1;                    // self loop
}

__global__ void k_hist(const int* __restrict__ ei) {
    int e = blockIdx.x * blockDim.x + threadIdx.x;
    if (e < EG) atomicAdd(&g_cnt[ei[EG + e]], 1);
}

__global__ void k_scan() {
    __shared__ int sums[1024];
    const int n = NN;
    const int chunk = (n + 1023) / 1024;
    int tid = threadIdx.x;
    int beg = tid * chunk;
    int end = min(beg + chunk, n);
    int s = 0;
    for (int i = beg; i < end; i++) s += g_cnt[i];
    sums[tid] = s;
    __syncthreads();
    for (int off = 1; off < 1024; off <<= 1) {
        int t = 0;
        if (tid >= off) t = sums[tid - off];
        __syncthreads();
        if (tid >= off) sums[tid] += t;
        __syncthreads();
    }
    int base = (tid > 0) ? sums[tid - 1] : 0;
    int run = base;
    for (int i = beg; i < end; i++) {
        g_rowptr[i] = run;
        run += g_cnt[i];
    }
    if (tid == 1023) g_rowptr[n] = sums[1023];
}

__global__ void k_prep() {
    int v = blockIdx.x * blockDim.x + threadIdx.x;
    if (v < NN) {
        g_dinv[v] = rsqrtf((float)g_cnt[v]);
        g_cursor[v] = g_rowptr[v];
    }
}

__global__ void k_fill(const int* __restrict__ ei) {
    int i = blockIdx.x * blockDim.x + threadIdx.x;
    if (i >= EE) return;
    int s, d;
    if (i < EG) { s = ei[i]; d = ei[EG + i]; }
    else        { s = d = i - EG; }
    int pos = atomicAdd(&g_cursor[d], 1);
    float w = (1.0f - ALPHA) * g_dinv[s] * g_dinv[d];  // fold 0.9 damping
    __half2 wh = __float2half2_rn(w);
    g_meta[pos] = make_uint2((unsigned)s, *reinterpret_cast<unsigned*>(&wh));
}

// ---------------------------------------------------------------------------
// GEMM:  Y[N,128] = (relu?)X[N,128] @ W[128,128]^T + b
// Writes fp16 anchor (x0) + fp8 iterate (gather source).
// ---------------------------------------------------------------------------
__global__ void k_gemm(const float* __restrict__ X, const float* __restrict__ W,
                       const float* __restrict__ bias,
                       __half* __restrict__ Yh, unsigned* __restrict__ Y8,
                       int relu_in) {
    extern __shared__ float sm[];
    float* WT = sm;               // [128*128]  WT[d*128+f]
    float* xs = sm + 128 * 128;   // [128][8] staging (input, then output)
    int tid = threadIdx.x;        // blockDim = 128

    for (int i = tid; i < 128 * 128; i += 128) {
        int f = i >> 7, d = i & 127;
        WT[(d << 7) | f] = W[i];
    }
    float bv = bias[tid];
    __syncthreads();

    for (int vb = blockIdx.x * 8; vb < NN; vb += gridDim.x * 8) {
#pragma unroll
        for (int r = 0; r < 8; r++) {
            float xv = X[(size_t)(vb + r) * 128 + tid];
            if (relu_in) xv = fmaxf(xv, 0.0f);
            xs[tid * 8 + r] = xv;
        }
        __syncthreads();
        float acc[8];
#pragma unroll
        for (int r = 0; r < 8; r++) acc[r] = bv;
#pragma unroll 16
        for (int d = 0; d < 128; d++) {
            float w = WT[(d << 7) + tid];
            float4 xlo = *(const float4*)(xs + d * 8);
            float4 xhi = *(const float4*)(xs + d * 8 + 4);
            acc[0] += xlo.x * w; acc[1] += xlo.y * w;
            acc[2] += xlo.z * w; acc[3] += xlo.w * w;
            acc[4] += xhi.x * w; acc[5] += xhi.y * w;
            acc[6] += xhi.z * w; acc[7] += xhi.w * w;
        }
        __syncthreads();                 // xs reads done; reuse as output stage
#pragma unroll
        for (int r = 0; r < 8; r++) {
            xs[tid * 8 + r] = acc[r];
            Yh[(size_t)(vb + r) * 128 + tid] = __float2half_rn(acc[r]);
        }
        __syncthreads();
        // fp8 pack: 8 rows x 32 uints
        for (int i = tid; i < 256; i += 128) {
            int r = i >> 5, c = i & 31;
            float f0 = xs[(4 * c + 0) * 8 + r];
            float f1 = xs[(4 * c + 1) * 8 + r];
            float f2 = xs[(4 * c + 2) * 8 + r];
            float f3 = xs[(4 * c + 3) * 8 + r];
            unsigned lo = __nv_cvt_float2_to_fp8x2(make_float2(f0, f1),
                                                   __NV_SATFINITE, __NV_E4M3);
            unsigned hi = __nv_cvt_float2_to_fp8x2(make_float2(f2, f3),
                                                   __NV_SATFINITE, __NV_E4M3);
            Y8[(size_t)(vb + r) * 32 + c] = lo | (hi << 16);
        }
        __syncthreads();
    }
}

// ---------------------------------------------------------------------------
// APPNP propagate step (fp8 gather, half2 FMA accumulate, weights pre-scaled
// by 0.9):   hout[v] = sum_e w'[e]*hin[col[e]] + 0.1*x0[v]
// warp per node; lane handles 4 features (4B fp8 load -> one 128B line/edge).
// ---------------------------------------------------------------------------
__device__ __forceinline__ void fp8x4_to_half2x2(unsigned u, __half2& v0, __half2& v1) {
    __half2_raw r0 = __nv_cvt_fp8x2_to_halfraw2((__nv_fp8x2_storage_t)(u & 0xFFFFu),
                                                __NV_E4M3);
    __half2_raw r1 = __nv_cvt_fp8x2_to_halfraw2((__nv_fp8x2_storage_t)(u >> 16),
                                                __NV_E4M3);
    v0 = *reinterpret_cast<__half2*>(&r0);
    v1 = *reinterpret_cast<__half2*>(&r1);
}

__global__ void k_prop(const unsigned* __restrict__ hin,
                       const uint2* __restrict__ x0,
                       unsigned* __restrict__ hout8,
                       float* __restrict__ hout_f) {
    int gw = (blockIdx.x * blockDim.x + threadIdx.x) >> 5;
    int lane = threadIdx.x & 31;
    if (gw >= NN) return;

    int beg = g_rowptr[gw];
    int end = g_rowptr[gw + 1];

    __half2 acc0 = __float2half2_rn(0.0f);
    __half2 acc1 = __float2half2_rn(0.0f);

    int e = beg;
    for (; e + 4 <= end; e += 4) {
        uint2 m0 = g_meta[e],     m1 = g_meta[e + 1];
        uint2 m2 = g_meta[e + 2], m3 = g_meta[e + 3];
        unsigned u0 = hin[(size_t)m0.x * 32 + lane];
        unsigned u1 = hin[(size_t)m1.x * 32 + lane];
        unsigned u2 = hin[(size_t)m2.x * 32 + lane];
        unsigned u3 = hin[(size_t)m3.x * 32 + lane];
        __half2 w0 = *reinterpret_cast<__half2*>(&m0.y);
        __half2 w1 = *reinterpret_cast<__half2*>(&m1.y);
        __half2 w2 = *reinterpret_cast<__half2*>(&m2.y);
        __half2 w3 = *reinterpret_cast<__half2*>(&m3.y);
        __half2 a, b;
        fp8x4_to_half2x2(u0, a, b);
        acc0 = __hfma2(w0, a, acc0); acc1 = __hfma2(w0, b, acc1);
        fp8x4_to_half2x2(u1, a, b);
        acc0 = __hfma2(w1, a, acc0); acc1 = __hfma2(w1, b, acc1);
        fp8x4_to_half2x2(u2, a, b);
        acc0 = __hfma2(w2, a, acc0); acc1 = __hfma2(w2, b, acc1);
        fp8x4_to_half2x2(u3, a, b);
        acc0 = __hfma2(w3, a, acc0); acc1 = __hfma2(w3, b, acc1);
    }
    for (; e < end; e++) {
        uint2 m = g_meta[e];
        unsigned u = hin[(size_t)m.x * 32 + lane];
        __half2 w = *reinterpret_cast<__half2*>(&m.y);
        __half2 a, b;
        fp8x4_to_half2x2(u, a, b);
        acc0 = __hfma2(w, a, acc0); acc1 = __hfma2(w, b, acc1);
    }

    float2 s0 = __half22float2(acc0);
    float2 s1 = __half22float2(acc1);

    uint2 xu = x0[(size_t)gw * 32 + lane];
    float2 x0a = __half22float2(*reinterpret_cast<__half2*>(&xu.x));
    float2 x0b = __half22float2(*reinterpret_cast<__half2*>(&xu.y));

    float r0 = s0.x + ALPHA * x0a.x;
    float r1 = s0.y + ALPHA * x0a.y;
    float r2 = s1.x + ALPHA * x0b.x;
    float r3 = s1.y + ALPHA * x0b.y;

    if (hout_f) {
        float4 o = make_float4(r0, r1, r2, r3);
        *(float4*)(hout_f + (size_t)gw * 128 + lane * 4) = o;
    } else {
        unsigned lo = __nv_cvt_float2_to_fp8x2(make_float2(r0, r1),
                                               __NV_SATFINITE, __NV_E4M3);
        unsigned hi = __nv_cvt_float2_to_fp8x2(make_float2(r2, r3),
                                               __NV_SATFINITE, __NV_E4M3);
        hout8[(size_t)gw * 32 + lane] = lo | (hi << 16);
    }
}

// ---------------------------------------------------------------------------
// Link layer: warp per pair (fp32 features).
// ---------------------------------------------------------------------------
__global__ void k_link(const float* __restrict__ h, const int* __restrict__ idx,
                       const float* __restrict__ W3, const float* __restrict__ b3,
                       float* __restrict__ out) {
    int gw = (blockIdx.x * blockDim.x + threadIdx.x) >> 5;
    int lane = threadIdx.x & 31;
    if (gw >= PP) return;

    float4 w00 = *(const float4*)(W3 + 4 * lane);
    float4 w01 = *(const float4*)(W3 + 128 + 4 * lane);
    float4 w10 = *(const float4*)(W3 + 256 + 4 * lane);
    float4 w11 = *(const float4*)(W3 + 256 + 128 + 4 * lane);

    int i0 = idx[2 * gw];
    int i1 = idx[2 * gw + 1];
    float4 a = *(const float4*)(h + (size_t)i0 * 128 + lane * 4);
    float4 b = *(const float4*)(h + (size_t)i1 * 128 + lane * 4);
    a.x = fmaxf(a.x, 0.f); a.y = fmaxf(a.y, 0.f);
    a.z = fmaxf(a.z, 0.f); a.w = fmaxf(a.w, 0.f);
    b.x = fmaxf(b.x, 0.f); b.y = fmaxf(b.y, 0.f);
    b.z = fmaxf(b.z, 0.f); b.w = fmaxf(b.w, 0.f);

    float l0 = a.x * w00.x + a.y * w00.y + a.z * w00.z + a.w * w00.w
             + b.x * w01.x + b.y * w01.y + b.z * w01.z + b.w * w01.w;
    float l1 = a.x * w10.x + a.y * w10.y + a.z * w10.z + a.w * w10.w
             + b.x * w11.x + b.y * w11.y + b.z * w11.z + b.w * w11.w;

#pragma unroll
    for (int off = 16; off; off >>= 1) {
        l0 += __shfl_xor_sync(0xffffffffu, l0, off);
        l1 += __shfl_xor_sync(0xffffffffu, l1, off);
    }
    if (lane == 0) {
        l0 += b3[0];
        l1 += b3[1];
        float m = fmaxf(l0, l1);
        float lse = m + logf(expf(l0 - m) + expf(l1 - m));
        out[2 * gw]     = l0 - lse;
        out[2 * gw + 1] = l1 - lse;
    }
}

// ---------------------------------------------------------------------------
// Launch
// ---------------------------------------------------------------------------
extern "C" void kernel_launch(void* const* d_in, const int* in_sizes, int n_in,
                              void* d_out, int out_size) {
    const float* x     = (const float*)d_in[0];
    const int*   ei    = (const int*)d_in[1];
    const int*   index = (const int*)d_in[2];
    const float* W1    = (const float*)d_in[3];
    const float* b1    = (const float*)d_in[4];
    const float* W2    = (const float*)d_in[5];
    const float* b2    = (const float*)d_in[6];
    const float* W3    = (const float*)d_in[7];
    const float* b3    = (const float*)d_in[8];
    float* out = (float*)d_out;

    float* Hg;
    uint2* X0;
    unsigned *F1, *F2;
    cudaGetSymbolAddress((void**)&Hg, g_Hg);
    cudaGetSymbolAddress((void**)&X0, g_x0h);
    cudaGetSymbolAddress((void**)&F1, g_f1);
    cudaGetSymbolAddress((void**)&F2, g_f2);

    const int gemm_smem = (128 * 128 + 128 * 8) * (int)sizeof(float);  // 69632
    cudaFuncSetAttribute(k_gemm, cudaFuncAttributeMaxDynamicSharedMemorySize,
                         gemm_smem);

    // ---- graph normalization / CSR build ----
    k_init<<<(NN + 255) / 256, 256>>>();
    k_hist<<<(EG + 255) / 256, 256>>>(ei);
    k_scan<<<1, 1024>>>();
    k_prep<<<(NN + 255) / 256, 256>>>();
    k_fill<<<(EE + 255) / 256, 256>>>(ei);

    const int prop_blocks = (NN * 32 + 255) / 256;   // 6250
    const int gemm_blocks = 444;

    // ---- layer 1: GEMM -> (x0 fp16, h0 fp8); 10x APPNP ----
    k_gemm<<<gemm_blocks, 128, gemm_smem>>>(x, W1, b1, (__half*)X0, F1, 0);
    {
        unsigned* bufs[2] = {F2, F1};
        const unsigned* cur = F1;
        for (int k = 0; k < 9; k++) {
            unsigned* o = bufs[k & 1];
            k_prop<<<prop_blocks, 256>>>(cur, X0, o, nullptr);
            cur = o;
        }
        k_prop<<<prop_blocks, 256>>>(cur, X0, nullptr, Hg);   // final -> fp32
    }

    // ---- layer 2: GEMM(relu) -> (x0 fp16, h0 fp8); 10x APPNP ----
    k_gemm<<<gemm_blocks, 128, gemm_smem>>>(Hg, W2, b2, (__half*)X0, F1, 1);
    {
        unsigned* bufs[2] = {F2, F1};
        const unsigned* cur = F1;
        for (int k = 0; k < 9; k++) {
            unsigned* o = bufs[k & 1];
            k_prop<<<prop_blocks, 256>>>(cur, X0, o, nullptr);
            cur = o;
        }
        k_prop<<<prop_blocks, 256>>>(cur, X0, nullptr, Hg);
    }

    // ---- link prediction head ----
    k_link<<<(PP * 32 + 255) / 256, 256>>>(Hg, index, W3, b3, out);
}

// round 15
// speedup vs baseline: 1.1353x; 1.1353x over previous
#include <cuda_runtime.h>
#include <cuda_fp16.h>
#include <cuda_fp8.h>
#include <math.h>

// Problem constants (match reference)
#define NN 50000
#define EG 800000
#define EE (EG + NN)   // edges + self loops = 850000
#define FD 128
#define PP 200000
#define ALPHA 0.1f

// ---------------------------------------------------------------------------
// Device scratch (no cudaMalloc allowed)
// ---------------------------------------------------------------------------
__device__ int   g_cnt[NN];                     // zero at load; re-zeroed in k_fill
__device__ int   g_rowptr[NN + 1];
__device__ int   g_cursor[NN];
__device__ float g_dinv[NN];
__device__ uint2 g_meta[EE];                    // (col, half2(0.9*w, 0.9*w))
__device__ uint4 g_x0h[(size_t)NN * 16];        // fp16 teleport anchor (8 half / uint4)
__device__ float g_Hg[(size_t)NN * FD];         // fp32 final-prop output
__device__ uint2 g_f1[(size_t)NN * 16];         // fp8 ping (8 e4m3 / uint2, 128B row)
__device__ uint2 g_f2[(size_t)NN * 16];         // fp8 pong

// ---------------------------------------------------------------------------
// CSR build (3 kernels)
// ---------------------------------------------------------------------------
// hist: self-loop + edge dst counts (g_cnt must be zero on entry; k_fill
// re-zeroes it so every kernel_launch invocation sees zeros).
__global__ void k_hist(const int* __restrict__ ei) {
    int i = blockIdx.x * blockDim.x + threadIdx.x;
    if (i < NN) atomicAdd(&g_cnt[i], 1);
    if (i < EG) atomicAdd(&g_cnt[ei[EG + i]], 1);
}

// single block: exclusive scan -> rowptr, then dinv + cursor
__global__ void k_scanprep() {
    __shared__ int sums[1024];
    const int n = NN;
    const int chunk = (n + 1023) / 1024;
    int tid = threadIdx.x;
    int beg = tid * chunk;
    int end = min(beg + chunk, n);
    int s = 0;
    for (int i = beg; i < end; i++) s += g_cnt[i];
    sums[tid] = s;
    __syncthreads();
    for (int off = 1; off < 1024; off <<= 1) {
        int t = 0;
        if (tid >= off) t = sums[tid - off];
        __syncthreads();
        if (tid >= off) sums[tid] += t;
        __syncthreads();
    }
    int base = (tid > 0) ? sums[tid - 1] : 0;
    int run = base;
    for (int i = beg; i < end; i++) {
        g_rowptr[i] = run;
        g_cursor[i] = run;
        g_dinv[i] = rsqrtf((float)g_cnt[i]);
        run += g_cnt[i];
    }
    if (tid == 1023) g_rowptr[n] = sums[1023];
}

// fill CSR; also re-zero g_cnt for the next invocation
__global__ void k_fill(const int* __restrict__ ei) {
    int i = blockIdx.x * blockDim.x + threadIdx.x;
    if (i < NN) g_cnt[i] = 0;
    if (i >= EE) return;
    int s, d;
    if (i < EG) { s = ei[i]; d = ei[EG + i]; }
    else        { s = d = i - EG; }
    int pos = atomicAdd(&g_cursor[d], 1);
    float w = (1.0f - ALPHA) * g_dinv[s] * g_dinv[d];  // fold 0.9 damping
    __half2 wh = __float2half2_rn(w);
    g_meta[pos] = make_uint2((unsigned)s, *reinterpret_cast<unsigned*>(&wh));
}

// ---------------------------------------------------------------------------
// GEMM:  Y[N,128] = (relu?)X[N,128] @ W[128,128]^T + b
// Writes fp16 anchor (x0) + fp8 iterate (gather source).
// ---------------------------------------------------------------------------
#define XS2_LD 132   // 8 rows x 132 floats (pad keeps 16B align, kills conflicts)

__global__ void k_gemm(const float* __restrict__ X, const float* __restrict__ W,
                       const float* __restrict__ bias,
                       __half* __restrict__ Yh, uint2* __restrict__ Y8,
                       int relu_in) {
    extern __shared__ float sm[];
    float* WT  = sm;                   // [128*128]  WT[d*128+f]
    float* xs  = sm + 128 * 128;       // [128][8] input staging
    float* xs2 = sm + 128 * 128;       // reused: [8][XS2_LD] output staging
    int tid = threadIdx.x;             // blockDim = 128

    for (int i = tid; i < 128 * 128; i += 128) {
        int f = i >> 7, d = i & 127;
        WT[(d << 7) | f] = W[i];
    }
    float bv = bias[tid];
    __syncthreads();

    for (int vb = blockIdx.x * 8; vb < NN; vb += gridDim.x * 8) {
#pragma unroll
        for (int r = 0; r < 8; r++) {
            float xv = X[(size_t)(vb + r) * 128 + tid];
            if (relu_in) xv = fmaxf(xv, 0.0f);
            xs[tid * 8 + r] = xv;
        }
        __syncthreads();
        float acc[8];
#pragma unroll
        for (int r = 0; r < 8; r++) acc[r] = bv;
#pragma unroll 16
        for (int d = 0; d < 128; d++) {
            float w = WT[(d << 7) + tid];
            float4 xlo = *(const float4*)(xs + d * 8);
            float4 xhi = *(const float4*)(xs + d * 8 + 4);
            acc[0] += xlo.x * w; acc[1] += xlo.y * w;
            acc[2] += xlo.z * w; acc[3] += xlo.w * w;
            acc[4] += xhi.x * w; acc[5] += xhi.y * w;
            acc[6] += xhi.z * w; acc[7] += xhi.w * w;
        }
        __syncthreads();                 // xs reads done; reuse as xs2
#pragma unroll
        for (int r = 0; r < 8; r++) {
            xs2[r * XS2_LD + tid] = acc[r];          // conflict-free (stride 1)
            Yh[(size_t)(vb + r) * 128 + tid] = __float2half_rn(acc[r]);
        }
        __syncthreads();
        // fp8 pack: 8 rows x 16 uint2; thread -> (r = tid>>4, c = tid&15)
        {
            int r = tid >> 4, c = tid & 15;
            float4 f0 = *(const float4*)(xs2 + r * XS2_LD + 8 * c);
            float4 f1 = *(const float4*)(xs2 + r * XS2_LD + 8 * c + 4);
            unsigned p0 = __nv_cvt_float2_to_fp8x2(make_float2(f0.x, f0.y),
                                                   __NV_SATFINITE, __NV_E4M3);
            unsigned p1 = __nv_cvt_float2_to_fp8x2(make_float2(f0.z, f0.w),
                                                   __NV_SATFINITE, __NV_E4M3);
            unsigned p2 = __nv_cvt_float2_to_fp8x2(make_float2(f1.x, f1.y),
                                                   __NV_SATFINITE, __NV_E4M3);
            unsigned p3 = __nv_cvt_float2_to_fp8x2(make_float2(f1.z, f1.w),
                                                   __NV_SATFINITE, __NV_E4M3);
            uint2 o;
            o.x = p0 | (p1 << 16);
            o.y = p2 | (p3 << 16);
            Y8[(size_t)(vb + r) * 16 + c] = o;
        }
        __syncthreads();
    }
}

// ---------------------------------------------------------------------------
// APPNP propagate: hout[v] = sum_e w'[e]*hin[col[e]] + 0.1*x0[v]
// (w' pre-scaled by 0.9). Warp per node, TWO edges per warp iteration:
// lanes 0-15 handle edge e, lanes 16-31 handle edge e+1.
// A fp8 row = 128B = 16 lanes x uint2 (8 e4m3 feats per lane).
// ---------------------------------------------------------------------------
__device__ __forceinline__ void fp8x8_fma(uint2 u, __half2 w,
                                          __half2& a0, __half2& a1,
                                          __half2& a2, __half2& a3) {
    __half2_raw r0 = __nv_cvt_fp8x2_to_halfraw2((__nv_fp8x2_storage_t)(u.x & 0xFFFFu), __NV_E4M3);
    __half2_raw r1 = __nv_cvt_fp8x2_to_halfraw2((__nv_fp8x2_storage_t)(u.x >> 16),     __NV_E4M3);
    __half2_raw r2 = __nv_cvt_fp8x2_to_halfraw2((__nv_fp8x2_storage_t)(u.y & 0xFFFFu), __NV_E4M3);
    __half2_raw r3 = __nv_cvt_fp8x2_to_halfraw2((__nv_fp8x2_storage_t)(u.y >> 16),     __NV_E4M3);
    a0 = __hfma2(w, *reinterpret_cast<__half2*>(&r0), a0);
    a1 = __hfma2(w, *reinterpret_cast<__half2*>(&r1), a1);
    a2 = __hfma2(w, *reinterpret_cast<__half2*>(&r2), a2);
    a3 = __hfma2(w, *reinterpret_cast<__half2*>(&r3), a3);
}

__device__ __forceinline__ __half2 h2_shfl_xor16(__half2 v) {
    unsigned u = *reinterpret_cast<unsigned*>(&v);
    u = __shfl_xor_sync(0xffffffffu, u, 16);
    return *reinterpret_cast<__half2*>(&u);
}

__global__ void k_prop(const uint2* __restrict__ hin,
                       const uint4* __restrict__ x0,
                       uint2* __restrict__ hout8,
                       float* __restrict__ hout_f) {
    int gw = (blockIdx.x * blockDim.x + threadIdx.x) >> 5;
    if (gw >= NN) return;
    int lane = threadIdx.x & 31;
    int h = lane >> 4;          // which edge of the pair
    int c = lane & 15;          // uint2 column within the 128B row

    int beg = g_rowptr[gw];
    int end = g_rowptr[gw + 1];

    const __half2 HZ = __float2half2_rn(0.0f);
    __half2 a0 = HZ, a1 = HZ, a2 = HZ, a3 = HZ;

    int e = beg;
    // main loop: 4 edges per iteration (2 per half-warp)
    for (; e + 4 <= end; e += 4) {
        uint2 mA = g_meta[e + h];
        uint2 mB = g_meta[e + 2 + h];
        uint2 uA = hin[(size_t)mA.x * 16 + c];
        uint2 uB = hin[(size_t)mB.x * 16 + c];
        __half2 wA = *reinterpret_cast<__half2*>(&mA.y);
        __half2 wB = *reinterpret_cast<__half2*>(&mB.y);
        fp8x8_fma(uA, wA, a0, a1, a2, a3);
        fp8x8_fma(uB, wB, a0, a1, a2, a3);
    }
    // tail: 2 edges per iteration, guarded
    for (; e < end; e += 2) {
        int idx = e + h;
        bool ok = idx < end;
        if (!ok) idx = end - 1;
        uint2 m = g_meta[idx];
        uint2 u = hin[(size_t)m.x * 16 + c];
        __half2 w = ok ? *reinterpret_cast<__half2*>(&m.y) : HZ;
        fp8x8_fma(u, w, a0, a1, a2, a3);
    }

    // merge the two half-warps (same node, same features)
    a0 = __hadd2(a0, h2_shfl_xor16(a0));
    a1 = __hadd2(a1, h2_shfl_xor16(a1));
    a2 = __hadd2(a2, h2_shfl_xor16(a2));
    a3 = __hadd2(a3, h2_shfl_xor16(a3));

    if (h == 0) {
        uint4 xu = x0[(size_t)gw * 16 + c];
        const __half2 al = __float2half2_rn(ALPHA);
        a0 = __hfma2(al, *reinterpret_cast<__half2*>(&xu.x), a0);
        a1 = __hfma2(al, *reinterpret_cast<__half2*>(&xu.y), a1);
        a2 = __hfma2(al, *reinterpret_cast<__half2*>(&xu.z), a2);
        a3 = __hfma2(al, *reinterpret_cast<__half2*>(&xu.w), a3);

        if (hout_f) {
            float2 f0 = __half22float2(a0);
            float2 f1 = __half22float2(a1);
            float2 f2 = __half22float2(a2);
            float2 f3 = __half22float2(a3);
            float* dst = hout_f + (size_t)gw * 128 + c * 8;
            *(float4*)(dst)     = make_float4(f0.x, f0.y, f1.x, f1.y);
            *(float4*)(dst + 4) = make_float4(f2.x, f2.y, f3.x, f3.y);
        } else {
            __half2_raw h0 = *reinterpret_cast<__half2_raw*>(&a0);
            __half2_raw h1 = *reinterpret_cast<__half2_raw*>(&a1);
            __half2_raw h2 = *reinterpret_cast<__half2_raw*>(&a2);
            __half2_raw h3 = *reinterpret_cast<__half2_raw*>(&a3);
            unsigned p0 = __nv_cvt_halfraw2_to_fp8x2(h0, __NV_SATFINITE, __NV_E4M3);
            unsigned p1 = __nv_cvt_halfraw2_to_fp8x2(h1, __NV_SATFINITE, __NV_E4M3);
            unsigned p2 = __nv_cvt_halfraw2_to_fp8x2(h2, __NV_SATFINITE, __NV_E4M3);
            unsigned p3 = __nv_cvt_halfraw2_to_fp8x2(h3, __NV_SATFINITE, __NV_E4M3);
            uint2 o;
            o.x = p0 | (p1 << 16);
            o.y = p2 | (p3 << 16);
            hout8[(size_t)gw * 16 + c] = o;
        }
    }
}

// ---------------------------------------------------------------------------
// Link layer: warp per pair (fp32 features).
// ---------------------------------------------------------------------------
__global__ void k_link(const float* __restrict__ h, const int* __restrict__ idx,
                       const float* __restrict__ W3, const float* __restrict__ b3,
                       float* __restrict__ out) {
    int gw = (blockIdx.x * blockDim.x + threadIdx.x) >> 5;
    int lane = threadIdx.x & 31;
    if (gw >= PP) return;

    float4 w00 = *(const float4*)(W3 + 4 * lane);
    float4 w01 = *(const float4*)(W3 + 128 + 4 * lane);
    float4 w10 = *(const float4*)(W3 + 256 + 4 * lane);
    float4 w11 = *(const float4*)(W3 + 256 + 128 + 4 * lane);

    int i0 = idx[2 * gw];
    int i1 = idx[2 * gw + 1];
    float4 a = *(const float4*)(h + (size_t)i0 * 128 + lane * 4);
    float4 b = *(const float4*)(h + (size_t)i1 * 128 + lane * 4);
    a.x = fmaxf(a.x, 0.f); a.y = fmaxf(a.y, 0.f);
    a.z = fmaxf(a.z, 0.f); a.w = fmaxf(a.w, 0.f);
    b.x = fmaxf(b.x, 0.f); b.y = fmaxf(b.y, 0.f);
    b.z = fmaxf(b.z, 0.f); b.w = fmaxf(b.w, 0.f);

    float l0 = a.x * w00.x + a.y * w00.y + a.z * w00.z + a.w * w00.w
             + b.x * w01.x + b.y * w01.y + b.z * w01.z + b.w * w01.w;
    float l1 = a.x * w10.x + a.y * w10.y + a.z * w10.z + a.w * w10.w
             + b.x * w11.x + b.y * w11.y + b.z * w11.z + b.w * w11.w;

#pragma unroll
    for (int off = 16; off; off >>= 1) {
        l0 += __shfl_xor_sync(0xffffffffu, l0, off);
        l1 += __shfl_xor_sync(0xffffffffu, l1, off);
    }
    if (lane == 0) {
        l0 += b3[0];
        l1 += b3[1];
        float m = fmaxf(l0, l1);
        float lse = m + logf(expf(l0 - m) + expf(l1 - m));
        out[2 * gw]     = l0 - lse;
        out[2 * gw + 1] = l1 - lse;
    }
}

// ---------------------------------------------------------------------------
// Launch
// ---------------------------------------------------------------------------
extern "C" void kernel_launch(void* const* d_in, const int* in_sizes, int n_in,
                              void* d_out, int out_size) {
    const float* x     = (const float*)d_in[0];
    const int*   ei    = (const int*)d_in[1];
    const int*   index = (const int*)d_in[2];
    const float* W1    = (const float*)d_in[3];
    const float* b1    = (const float*)d_in[4];
    const float* W2    = (const float*)d_in[5];
    const float* b2    = (const float*)d_in[6];
    const float* W3    = (const float*)d_in[7];
    const float* b3    = (const float*)d_in[8];
    float* out = (float*)d_out;

    float* Hg;
    uint4* X0;
    uint2 *F1, *F2;
    cudaGetSymbolAddress((void**)&Hg, g_Hg);
    cudaGetSymbolAddress((void**)&X0, g_x0h);
    cudaGetSymbolAddress((void**)&F1, g_f1);
    cudaGetSymbolAddress((void**)&F2, g_f2);

    const int gemm_smem = (128 * 128 + 8 * XS2_LD) * (int)sizeof(float);  // 69760
    cudaFuncSetAttribute(k_gemm, cudaFuncAttributeMaxDynamicSharedMemorySize,
                         gemm_smem);

    // ---- graph normalization / CSR build (3 launches) ----
    k_hist<<<(EG + 255) / 256, 256>>>(ei);
    k_scanprep<<<1, 1024>>>();
    k_fill<<<(EE + 255) / 256, 256>>>(ei);

    const int prop_blocks = (NN * 32 + 255) / 256;   // 6250
    const int gemm_blocks = 444;

    // ---- layer 1: GEMM -> (x0 fp16, h0 fp8); 10x APPNP ----
    k_gemm<<<gemm_blocks, 128, gemm_smem>>>(x, W1, b1, (__half*)X0, F1, 0);
    {
        uint2* bufs[2] = {F2, F1};
        const uint2* cur = F1;
        for (int k = 0; k < 9; k++) {
            uint2* o = bufs[k & 1];
            k_prop<<<prop_blocks, 256>>>(cur, X0, o, nullptr);
            cur = o;
        }
        k_prop<<<prop_blocks, 256>>>(cur, X0, nullptr, Hg);   // final -> fp32
    }

    // ---- layer 2: GEMM(relu) -> (x0 fp16, h0 fp8); 10x APPNP ----
    k_gemm<<<gemm_blocks, 128, gemm_smem>>>(Hg, W2, b2, (__half*)X0, F1, 1);
    {
        uint2* bufs[2] = {F2, F1};
        const uint2* cur = F1;
        for (int k = 0; k < 9; k++) {
            uint2* o = bufs[k & 1];
            k_prop<<<prop_blocks, 256>>>(cur, X0, o, nullptr);
            cur = o;
        }
        k_prop<<<prop_blocks, 256>>>(cur, X0, nullptr, Hg);
    }

    // ---- link prediction head ----
    k_link<<<(PP * 32 + 255) / 256, 256>>>(Hg, index, W3, b3, out);
}

// round 16
// speedup vs baseline: 1.1389x; 1.0032x over previous
#include <cuda_runtime.h>
#include <cuda_fp16.h>
#include <cuda_fp8.h>
#include <math.h>

// Problem constants (match reference)
#define NN 50000
#define EG 800000
#define EE (EG + NN)   // edges + self loops = 850000
#define FD 128
#define PP 200000
#define ALPHA 0.1f

// ---------------------------------------------------------------------------
// Device scratch (no cudaMalloc allowed)
// ---------------------------------------------------------------------------
__device__ int   g_cnt[NN];                     // zero at load; re-zeroed in k_fill
__device__ int   g_rowptr[NN + 1];
__device__ int   g_cursor[NN];
__device__ float g_dinv[NN];
__device__ uint2 g_meta[EE];                    // (col, half2(0.9*w, 0.9*w))
__device__ uint4 g_x0h[(size_t)NN * 16];        // fp16 teleport anchor (8 half / uint4)
__device__ float g_Hg[(size_t)NN * FD];         // fp32 final-prop output
__device__ uint2 g_f1[(size_t)NN * 16];         // fp8 ping (8 e4m3 / uint2, 128B row)
__device__ uint2 g_f2[(size_t)NN * 16];         // fp8 pong

// ---------------------------------------------------------------------------
// CSR build (3 kernels)
// ---------------------------------------------------------------------------
// hist: self-loop + edge dst counts (g_cnt must be zero on entry; k_fill
// re-zeroes it so every kernel_launch invocation sees zeros).
__global__ void k_hist(const int* __restrict__ ei) {
    int i = blockIdx.x * blockDim.x + threadIdx.x;
    if (i < NN) atomicAdd(&g_cnt[i], 1);
    if (i < EG) atomicAdd(&g_cnt[ei[EG + i]], 1);
}

// single block: exclusive scan -> rowptr, then dinv + cursor
__global__ void k_scanprep() {
    __shared__ int sums[1024];
    const int n = NN;
    const int chunk = (n + 1023) / 1024;
    int tid = threadIdx.x;
    int beg = tid * chunk;
    int end = min(beg + chunk, n);
    int s = 0;
    for (int i = beg; i < end; i++) s += g_cnt[i];
    sums[tid] = s;
    __syncthreads();
    for (int off = 1; off < 1024; off <<= 1) {
        int t = 0;
        if (tid >= off) t = sums[tid - off];
        __syncthreads();
        if (tid >= off) sums[tid] += t;
        __syncthreads();
    }
    int base = (tid > 0) ? sums[tid - 1] : 0;
    int run = base;
    for (int i = beg; i < end; i++) {
        g_rowptr[i] = run;
        g_cursor[i] = run;
        g_dinv[i] = rsqrtf((float)g_cnt[i]);
        run += g_cnt[i];
    }
    if (tid == 1023) g_rowptr[n] = sums[1023];
}

// fill CSR; also re-zero g_cnt for the next invocation
__global__ void k_fill(const int* __restrict__ ei) {
    int i = blockIdx.x * blockDim.x + threadIdx.x;
    if (i < NN) g_cnt[i] = 0;
    if (i >= EE) return;
    int s, d;
    if (i < EG) { s = ei[i]; d = ei[EG + i]; }
    else        { s = d = i - EG; }
    int pos = atomicAdd(&g_cursor[d], 1);
    float w = (1.0f - ALPHA) * g_dinv[s] * g_dinv[d];  // fold 0.9 damping
    __half2 wh = __float2half2_rn(w);
    g_meta[pos] = make_uint2((unsigned)s, *reinterpret_cast<unsigned*>(&wh));
}

// ---------------------------------------------------------------------------
// GEMM:  Y[N,128] = (relu?)X[N,128] @ W[128,128]^T + b
// Writes fp16 anchor (x0) + fp8 iterate (gather source).
// ---------------------------------------------------------------------------
#define XS2_LD 132   // 8 rows x 132 floats (pad keeps 16B align, kills conflicts)

__global__ void k_gemm(const float* __restrict__ X, const float* __restrict__ W,
                       const float* __restrict__ bias,
                       __half* __restrict__ Yh, uint2* __restrict__ Y8,
                       int relu_in) {
    extern __shared__ float sm[];
    float* WT  = sm;                   // [128*128]  WT[d*128+f]
    float* xs  = sm + 128 * 128;       // [128][8] input staging
    float* xs2 = sm + 128 * 128;       // reused: [8][XS2_LD] output staging
    int tid = threadIdx.x;             // blockDim = 128

    for (int i = tid; i < 128 * 128; i += 128) {
        int f = i >> 7, d = i & 127;
        WT[(d << 7) | f] = W[i];
    }
    float bv = bias[tid];
    __syncthreads();

    for (int vb = blockIdx.x * 8; vb < NN; vb += gridDim.x * 8) {
#pragma unroll
        for (int r = 0; r < 8; r++) {
            float xv = X[(size_t)(vb + r) * 128 + tid];
            if (relu_in) xv = fmaxf(xv, 0.0f);
            xs[tid * 8 + r] = xv;
        }
        __syncthreads();
        float acc[8];
#pragma unroll
        for (int r = 0; r < 8; r++) acc[r] = bv;
#pragma unroll 16
        for (int d = 0; d < 128; d++) {
            float w = WT[(d << 7) + tid];
            float4 xlo = *(const float4*)(xs + d * 8);
            float4 xhi = *(const float4*)(xs + d * 8 + 4);
            acc[0] += xlo.x * w; acc[1] += xlo.y * w;
            acc[2] += xlo.z * w; acc[3] += xlo.w * w;
            acc[4] += xhi.x * w; acc[5] += xhi.y * w;
            acc[6] += xhi.z * w; acc[7] += xhi.w * w;
        }
        __syncthreads();                 // xs reads done; reuse as xs2
#pragma unroll
        for (int r = 0; r < 8; r++) {
            xs2[r * XS2_LD + tid] = acc[r];          // conflict-free (stride 1)
            Yh[(size_t)(vb + r) * 128 + tid] = __float2half_rn(acc[r]);
        }
        __syncthreads();
        // fp8 pack: 8 rows x 16 uint2; thread -> (r = tid>>4, c = tid&15)
        {
            int r = tid >> 4, c = tid & 15;
            float4 f0 = *(const float4*)(xs2 + r * XS2_LD + 8 * c);
            float4 f1 = *(const float4*)(xs2 + r * XS2_LD + 8 * c + 4);
            unsigned p0 = __nv_cvt_float2_to_fp8x2(make_float2(f0.x, f0.y),
                                                   __NV_SATFINITE, __NV_E4M3);
            unsigned p1 = __nv_cvt_float2_to_fp8x2(make_float2(f0.z, f0.w),
                                                   __NV_SATFINITE, __NV_E4M3);
            unsigned p2 = __nv_cvt_float2_to_fp8x2(make_float2(f1.x, f1.y),
                                                   __NV_SATFINITE, __NV_E4M3);
            unsigned p3 = __nv_cvt_float2_to_fp8x2(make_float2(f1.z, f1.w),
                                                   __NV_SATFINITE, __NV_E4M3);
            uint2 o;
            o.x = p0 | (p1 << 16);
            o.y = p2 | (p3 << 16);
            Y8[(size_t)(vb + r) * 16 + c] = o;
        }
        __syncthreads();
    }
}

// ---------------------------------------------------------------------------
// APPNP propagate: hout[v] = sum_e w'[e]*hin[col[e]] + 0.1*x0[v]
// (w' pre-scaled by 0.9). Warp per node, TWO edges per warp iteration:
// lanes 0-15 handle edge e, lanes 16-31 handle edge e+1.
// A fp8 row = 128B = 16 lanes x uint2 (8 e4m3 feats per lane).
// ---------------------------------------------------------------------------
__device__ __forceinline__ void fp8x8_fma(uint2 u, __half2 w,
                                          __half2& a0, __half2& a1,
                                          __half2& a2, __half2& a3) {
    __half2_raw r0 = __nv_cvt_fp8x2_to_halfraw2((__nv_fp8x2_storage_t)(u.x & 0xFFFFu), __NV_E4M3);
    __half2_raw r1 = __nv_cvt_fp8x2_to_halfraw2((__nv_fp8x2_storage_t)(u.x >> 16),     __NV_E4M3);
    __half2_raw r2 = __nv_cvt_fp8x2_to_halfraw2((__nv_fp8x2_storage_t)(u.y & 0xFFFFu), __NV_E4M3);
    __half2_raw r3 = __nv_cvt_fp8x2_to_halfraw2((__nv_fp8x2_storage_t)(u.y >> 16),     __NV_E4M3);
    a0 = __hfma2(w, *reinterpret_cast<__half2*>(&r0), a0);
    a1 = __hfma2(w, *reinterpret_cast<__half2*>(&r1), a1);
    a2 = __hfma2(w, *reinterpret_cast<__half2*>(&r2), a2);
    a3 = __hfma2(w, *reinterpret_cast<__half2*>(&r3), a3);
}

__device__ __forceinline__ __half2 h2_shfl_xor16(__half2 v) {
    unsigned u = *reinterpret_cast<unsigned*>(&v);
    u = __shfl_xor_sync(0xffffffffu, u, 16);
    return *reinterpret_cast<__half2*>(&u);
}

__global__ void k_prop(const uint2* __restrict__ hin,
                       const uint4* __restrict__ x0,
                       uint2* __restrict__ hout8,
                       float* __restrict__ hout_f) {
    int gw = (blockIdx.x * blockDim.x + threadIdx.x) >> 5;
    if (gw >= NN) return;
    int lane = threadIdx.x & 31;
    int h = lane >> 4;          // which edge of the pair
    int c = lane & 15;          // uint2 column within the 128B row

    int beg = g_rowptr[gw];
    int end = g_rowptr[gw + 1];

    const __half2 HZ = __float2half2_rn(0.0f);
    __half2 a0 = HZ, a1 = HZ, a2 = HZ, a3 = HZ;

    int e = beg;
    // main loop: 4 edges per iteration (2 per half-warp)
    for (; e + 4 <= end; e += 4) {
        uint2 mA = g_meta[e + h];
        uint2 mB = g_meta[e + 2 + h];
        uint2 uA = hin[(size_t)mA.x * 16 + c];
        uint2 uB = hin[(size_t)mB.x * 16 + c];
        __half2 wA = *reinterpret_cast<__half2*>(&mA.y);
        __half2 wB = *reinterpret_cast<__half2*>(&mB.y);
        fp8x8_fma(uA, wA, a0, a1, a2, a3);
        fp8x8_fma(uB, wB, a0, a1, a2, a3);
    }
    // tail: 2 edges per iteration, guarded
    for (; e < end; e += 2) {
        int idx = e + h;
        bool ok = idx < end;
        if (!ok) idx = end - 1;
        uint2 m = g_meta[idx];
        uint2 u = hin[(size_t)m.x * 16 + c];
        __half2 w = ok ? *reinterpret_cast<__half2*>(&m.y) : HZ;
        fp8x8_fma(u, w, a0, a1, a2, a3);
    }

    // merge the two half-warps (same node, same features)
    a0 = __hadd2(a0, h2_shfl_xor16(a0));
    a1 = __hadd2(a1, h2_shfl_xor16(a1));
    a2 = __hadd2(a2, h2_shfl_xor16(a2));
    a3 = __hadd2(a3, h2_shfl_xor16(a3));

    if (h == 0) {
        uint4 xu = x0[(size_t)gw * 16 + c];
        const __half2 al = __float2half2_rn(ALPHA);
        a0 = __hfma2(al, *reinterpret_cast<__half2*>(&xu.x), a0);
        a1 = __hfma2(al, *reinterpret_cast<__half2*>(&xu.y), a1);
        a2 = __hfma2(al, *reinterpret_cast<__half2*>(&xu.z), a2);
        a3 = __hfma2(al, *reinterpret_cast<__half2*>(&xu.w), a3);

        if (hout_f) {
            float2 f0 = __half22float2(a0);
            float2 f1 = __half22float2(a1);
            float2 f2 = __half22float2(a2);
            float2 f3 = __half22float2(a3);
            float* dst = hout_f + (size_t)gw * 128 + c * 8;
            *(float4*)(dst)     = make_float4(f0.x, f0.y, f1.x, f1.y);
            *(float4*)(dst + 4) = make_float4(f2.x, f2.y, f3.x, f3.y);
        } else {
            __half2_raw h0 = *reinterpret_cast<__half2_raw*>(&a0);
            __half2_raw h1 = *reinterpret_cast<__half2_raw*>(&a1);
            __half2_raw h2 = *reinterpret_cast<__half2_raw*>(&a2);
            __half2_raw h3 = *reinterpret_cast<__half2_raw*>(&a3);
            unsigned p0 = __nv_cvt_halfraw2_to_fp8x2(h0, __NV_SATFINITE, __NV_E4M3);
            unsigned p1 = __nv_cvt_halfraw2_to_fp8x2(h1, __NV_SATFINITE, __NV_E4M3);
            unsigned p2 = __nv_cvt_halfraw2_to_fp8x2(h2, __NV_SATFINITE, __NV_E4M3);
            unsigned p3 = __nv_cvt_halfraw2_to_fp8x2(h3, __NV_SATFINITE, __NV_E4M3);
            uint2 o;
            o.x = p0 | (p1 << 16);
            o.y = p2 | (p3 << 16);
            hout8[(size_t)gw * 16 + c] = o;
        }
    }
}

// ---------------------------------------------------------------------------
// Link layer: warp per pair (fp32 features).
// ---------------------------------------------------------------------------
__global__ void k_link(const float* __restrict__ h, const int* __restrict__ idx,
                       const float* __restrict__ W3, const float* __restrict__ b3,
                       float* __restrict__ out) {
    int gw = (blockIdx.x * blockDim.x + threadIdx.x) >> 5;
    int lane = threadIdx.x & 31;
    if (gw >= PP) return;

    float4 w00 = *(const float4*)(W3 + 4 * lane);
    float4 w01 = *(const float4*)(W3 + 128 + 4 * lane);
    float4 w10 = *(const float4*)(W3 + 256 + 4 * lane);
    float4 w11 = *(const float4*)(W3 + 256 + 128 + 4 * lane);

    int i0 = idx[2 * gw];
    int i1 = idx[2 * gw + 1];
    float4 a = *(const float4*)(h + (size_t)i0 * 128 + lane * 4);
    float4 b = *(const float4*)(h + (size_t)i1 * 128 + lane * 4);
    a.x = fmaxf(a.x, 0.f); a.y = fmaxf(a.y, 0.f);
    a.z = fmaxf(a.z, 0.f); a.w = fmaxf(a.w, 0.f);
    b.x = fmaxf(b.x, 0.f); b.y = fmaxf(b.y, 0.f);
    b.z = fmaxf(b.z, 0.f); b.w = fmaxf(b.w, 0.f);

    float l0 = a.x * w00.x + a.y * w00.y + a.z * w00.z + a.w * w00.w
             + b.x * w01.x + b.y * w01.y + b.z * w01.z + b.w * w01.w;
    float l1 = a.x * w10.x + a.y * w10.y + a.z * w10.z + a.w * w10.w
             + b.x * w11.x + b.y * w11.y + b.z * w11.z + b.w * w11.w;

#pragma unroll
    for (int off = 16; off; off >>= 1) {
        l0 += __shfl_xor_sync(0xffffffffu, l0, off);
        l1 += __shfl_xor_sync(0xffffffffu, l1, off);
    }
    if (lane == 0) {
        l0 += b3[0];
        l1 += b3[1];
        float m = fmaxf(l0, l1);
        float lse = m + logf(expf(l0 - m) + expf(l1 - m));
        out[2 * gw]     = l0 - lse;
        out[2 * gw + 1] = l1 - lse;
    }
}

// ---------------------------------------------------------------------------
// Launch
// ---------------------------------------------------------------------------
extern "C" void kernel_launch(void* const* d_in, const int* in_sizes, int n_in,
                              void* d_out, int out_size) {
    const float* x     = (const float*)d_in[0];
    const int*   ei    = (const int*)d_in[1];
    const int*   index = (const int*)d_in[2];
    const float* W1    = (const float*)d_in[3];
    const float* b1    = (const float*)d_in[4];
    const float* W2    = (const float*)d_in[5];
    const float* b2    = (const float*)d_in[6];
    const float* W3    = (const float*)d_in[7];
    const float* b3    = (const float*)d_in[8];
    float* out = (float*)d_out;

    float* Hg;
    uint4* X0;
    uint2 *F1, *F2;
    cudaGetSymbolAddress((void**)&Hg, g_Hg);
    cudaGetSymbolAddress((void**)&X0, g_x0h);
    cudaGetSymbolAddress((void**)&F1, g_f1);
    cudaGetSymbolAddress((void**)&F2, g_f2);

    const int gemm_smem = (128 * 128 + 8 * XS2_LD) * (int)sizeof(float);  // 69760
    cudaFuncSetAttribute(k_gemm, cudaFuncAttributeMaxDynamicSharedMemorySize,
                         gemm_smem);

    // ---- graph normalization / CSR build (3 launches) ----
    k_hist<<<(EG + 255) / 256, 256>>>(ei);
    k_scanprep<<<1, 1024>>>();
    k_fill<<<(EE + 255) / 256, 256>>>(ei);

    const int prop_blocks = (NN * 32 + 255) / 256;   // 6250
    const int gemm_blocks = 444;

    // ---- layer 1: GEMM -> (x0 fp16, h0 fp8); 10x APPNP ----
    k_gemm<<<gemm_blocks, 128, gemm_smem>>>(x, W1, b1, (__half*)X0, F1, 0);
    {
        uint2* bufs[2] = {F2, F1};
        const uint2* cur = F1;
        for (int k = 0; k < 9; k++) {
            uint2* o = bufs[k & 1];
            k_prop<<<prop_blocks, 256>>>(cur, X0, o, nullptr);
            cur = o;
        }
        k_prop<<<prop_blocks, 256>>>(cur, X0, nullptr, Hg);   // final -> fp32
    }

    // ---- layer 2: GEMM(relu) -> (x0 fp16, h0 fp8); 10x APPNP ----
    k_gemm<<<gemm_blocks, 128, gemm_smem>>>(Hg, W2, b2, (__half*)X0, F1, 1);
    {
        uint2* bufs[2] = {F2, F1};
        const uint2* cur = F1;
        for (int k = 0; k < 9; k++) {
            uint2* o = bufs[k & 1];
            k_prop<<<prop_blocks, 256>>>(cur, X0, o, nullptr);
            cur = o;
        }
        k_prop<<<prop_blocks, 256>>>(cur, X0, nullptr, Hg);
    }

    // ---- link prediction head ----
    k_link<<<(PP * 32 + 255) / 256, 256>>>(Hg, index, W3, b3, out);
}